// round 2
// baseline (speedup 1.0000x reference)
#include <cuda_runtime.h>

#define D 128
#define MAXN 100000

// Scratch buffers (allocation-free rule: __device__ globals)
__device__ float g_h[(size_t)MAXN * D];   // agg buffer (init = x, scatter-added)
__device__ float g_t[(size_t)MAXN * D];   // hidden after first linear
__device__ float g_o[(size_t)MAXN * D];   // layer-1 output
__device__ float g_wt[4][D * D];          // transposed weights: g_wt[w][k*128+c] = W[c*128+k]

// ---------------------------------------------------------------------------
// Transpose all 4 weight matrices once per call (tiny).
__global__ void transpose_w_kernel(const float* __restrict__ w0,
                                   const float* __restrict__ w1,
                                   const float* __restrict__ w2,
                                   const float* __restrict__ w3) {
    int i = blockIdx.x * blockDim.x + threadIdx.x;   // 0 .. 4*16384-1
    if (i >= 4 * D * D) return;
    int widx = i >> 14;
    int k = (i >> 7) & 127;
    int c = i & 127;
    const float* w = (widx == 0) ? w0 : (widx == 1) ? w1 : (widx == 2) ? w2 : w3;
    g_wt[widx][k * D + c] = w[c * D + k];
}

// ---------------------------------------------------------------------------
// float4 copy (init agg buffer with x so h = x + sum_neighbors)
__global__ void copy_kernel(const float* __restrict__ src, float* __restrict__ dst, int n4) {
    int i = blockIdx.x * blockDim.x + threadIdx.x;
    if (i < n4) ((float4*)dst)[i] = ((const float4*)src)[i];
}

// ---------------------------------------------------------------------------
// Scatter-add: one warp per edge. Each lane handles one float4 (128 floats/row).
// edge_index is INT32 on device (JAX without x64 truncates int64 -> int32).
// Uses vector reduction red.global.add.v4.f32 (sm_90+) to quarter atomic op count.
__global__ void scatter_kernel(const float* __restrict__ x,
                               const int* __restrict__ ei,
                               float* __restrict__ agg, int E) {
    int w = (int)((blockIdx.x * (unsigned)blockDim.x + threadIdx.x) >> 5);
    if (w >= E) return;
    int lane = threadIdx.x & 31;
    int s = __ldg(ei + w);
    int d = __ldg(ei + E + w);
    float4 v = ((const float4*)x)[(long long)s * 32 + lane];
    const float* p = agg + (long long)d * D + lane * 4;
    asm volatile("red.global.add.v4.f32 [%0], {%1,%2,%3,%4};"
                 :: "l"(p), "f"(v.x), "f"(v.y), "f"(v.z), "f"(v.w)
                 : "memory");
}

// ---------------------------------------------------------------------------
// GEMM: out[r][c] = act( sum_k in[r][k] * Wt[k][c] + bias[c] )
// Block: 128 rows x 128 cols, 256 threads, 8x8 register tile per thread.
// Per-thread rows strided by 16 (row_i = ty + 16*i) -> conflict-free a-loads.
// Smem strides padded to 132 floats (16B-aligned, bank-shifted).
#define XS_STRIDE 132
#define WS_STRIDE 132

__global__ __launch_bounds__(256, 1)
void gemm_kernel(const float* __restrict__ in,
                 const float* __restrict__ wt,     // [k][c] 128x128 row-major
                 const float* __restrict__ bias,
                 float* __restrict__ out,
                 int nrows, int relu) {
    extern __shared__ float sm[];
    float* Xs = sm;                   // [128][XS_STRIDE]
    float* Ws = sm + 128 * XS_STRIDE; // [128][WS_STRIDE]

    int tid = threadIdx.x;
    int row0 = blockIdx.x * 128;

    // Load X tile (float4, coalesced; zero-fill out-of-range rows)
    for (int i = tid; i < 128 * 32; i += 256) {
        int r = i >> 5, kq = i & 31;
        float4 v = make_float4(0.f, 0.f, 0.f, 0.f);
        if (row0 + r < nrows)
            v = ((const float4*)in)[(long long)(row0 + r) * 32 + kq];
        *(float4*)(Xs + r * XS_STRIDE + kq * 4) = v;
    }
    // Load Wt tile (already transposed in gmem -> coalesced, conflict-free)
    for (int i = tid; i < 128 * 32; i += 256) {
        int k = i >> 5, cq = i & 31;
        *(float4*)(Ws + k * WS_STRIDE + cq * 4) = ((const float4*)wt)[i];
    }
    __syncthreads();

    int tx = tid & 15, ty = tid >> 4;
    int c0 = tx * 8;

    float acc[8][8];
#pragma unroll
    for (int i = 0; i < 8; i++)
#pragma unroll
        for (int j = 0; j < 8; j++) acc[i][j] = 0.f;

#pragma unroll 4
    for (int k = 0; k < 128; ++k) {
        float4 b0 = *(const float4*)(Ws + k * WS_STRIDE + c0);
        float4 b1 = *(const float4*)(Ws + k * WS_STRIDE + c0 + 4);
        float b[8] = {b0.x, b0.y, b0.z, b0.w, b1.x, b1.y, b1.z, b1.w};
        float a[8];
#pragma unroll
        for (int i = 0; i < 8; i++) a[i] = Xs[(ty + 16 * i) * XS_STRIDE + k];
#pragma unroll
        for (int i = 0; i < 8; i++)
#pragma unroll
            for (int j = 0; j < 8; j++) acc[i][j] += a[i] * b[j];
    }

    float bv[8];
#pragma unroll
    for (int j = 0; j < 8; j++) bv[j] = __ldg(bias + c0 + j);

#pragma unroll
    for (int i = 0; i < 8; i++) {
        int r = row0 + ty + 16 * i;
        if (r >= nrows) continue;
        float o[8];
#pragma unroll
        for (int j = 0; j < 8; j++) {
            float v = acc[i][j] + bv[j];
            if (relu) v = fmaxf(v, 0.f);
            o[j] = v;
        }
        float4* po = (float4*)(out + (long long)r * D + c0);
        po[0] = make_float4(o[0], o[1], o[2], o[3]);
        po[1] = make_float4(o[4], o[5], o[6], o[7]);
    }
}

// ---------------------------------------------------------------------------
extern "C" void kernel_launch(void* const* d_in, const int* in_sizes, int n_in,
                              void* d_out, int out_size) {
    const float* x        = (const float*)d_in[0];
    const int*   ei       = (const int*)d_in[1];
    const float* w0a = (const float*)d_in[2];
    const float* b0a = (const float*)d_in[3];
    const float* w0b = (const float*)d_in[4];
    const float* b0b = (const float*)d_in[5];
    const float* w1a = (const float*)d_in[6];
    const float* b1a = (const float*)d_in[7];
    const float* w1b = (const float*)d_in[8];
    const float* b1b = (const float*)d_in[9];

    int N = in_sizes[0] / D;
    int E = in_sizes[1] / 2;

    float *p_h, *p_t, *p_o, *p_wt;
    cudaGetSymbolAddress((void**)&p_h,  g_h);
    cudaGetSymbolAddress((void**)&p_t,  g_t);
    cudaGetSymbolAddress((void**)&p_o,  g_o);
    cudaGetSymbolAddress((void**)&p_wt, g_wt);

    const int smem = (128 * XS_STRIDE + 128 * WS_STRIDE) * (int)sizeof(float);
    cudaFuncSetAttribute(gemm_kernel, cudaFuncAttributeMaxDynamicSharedMemorySize, smem);

    int n4 = N * (D / 4);
    int copyBlocks = (n4 + 255) / 256;
    int scatBlocks = (E + 7) / 8;              // 8 warps (edges) per 256-thread block
    int gemmBlocks = (N + 127) / 128;

    // Transpose all weights once
    transpose_w_kernel<<<(4 * D * D + 255) / 256, 256>>>(w0a, w0b, w1a, w1b);

    // ---- Layer 1 ----
    copy_kernel<<<copyBlocks, 256>>>(x, p_h, n4);
    scatter_kernel<<<scatBlocks, 256>>>(x, ei, p_h, E);
    gemm_kernel<<<gemmBlocks, 256, smem>>>(p_h, p_wt + 0 * D * D, b0a, p_t, N, 1);
    gemm_kernel<<<gemmBlocks, 256, smem>>>(p_t, p_wt + 1 * D * D, b0b, p_o, N, 0);

    // ---- Layer 2 ----
    copy_kernel<<<copyBlocks, 256>>>(p_o, p_h, n4);
    scatter_kernel<<<scatBlocks, 256>>>(p_o, ei, p_h, E);
    gemm_kernel<<<gemmBlocks, 256, smem>>>(p_h, p_wt + 2 * D * D, b1a, p_t, N, 1);
    gemm_kernel<<<gemmBlocks, 256, smem>>>(p_t, p_wt + 3 * D * D, b1b, (float*)d_out, N, 0);
}

// round 3
// speedup vs baseline: 1.2760x; 1.2760x over previous
#include <cuda_runtime.h>
#include <cstdint>

#define D 128
#define MAXN 100000

// Scratch buffers (allocation-free rule: __device__ globals)
__device__ float g_h[(size_t)MAXN * D];   // agg buffer (init = x, scatter-added)
__device__ float g_t[(size_t)MAXN * D];   // hidden after first linear
__device__ float g_o[(size_t)MAXN * D];   // layer-1 output
__device__ float g_wt[4][D * D];          // transposed weights: g_wt[w][k*128+c] = W[c*128+k]

// ---------------------------------------------------------------------------
__global__ void transpose_w_kernel(const float* __restrict__ w0,
                                   const float* __restrict__ w1,
                                   const float* __restrict__ w2,
                                   const float* __restrict__ w3) {
    int i = blockIdx.x * blockDim.x + threadIdx.x;
    if (i >= 4 * D * D) return;
    int widx = i >> 14;
    int k = (i >> 7) & 127;
    int c = i & 127;
    const float* w = (widx == 0) ? w0 : (widx == 1) ? w1 : (widx == 2) ? w2 : w3;
    g_wt[widx][k * D + c] = w[c * D + k];
}

// ---------------------------------------------------------------------------
__global__ void copy_kernel(const float* __restrict__ src, float* __restrict__ dst, int n4) {
    int i = blockIdx.x * blockDim.x + threadIdx.x;
    if (i < n4) ((float4*)dst)[i] = ((const float4*)src)[i];
}

// ---------------------------------------------------------------------------
// Scatter-add: one warp per edge, red.global.add.v4.f32. edge_index is int32.
__global__ void scatter_kernel(const float* __restrict__ x,
                               const int* __restrict__ ei,
                               float* __restrict__ agg, int E) {
    int w = (int)((blockIdx.x * (unsigned)blockDim.x + threadIdx.x) >> 5);
    if (w >= E) return;
    int lane = threadIdx.x & 31;
    int s = __ldg(ei + w);
    int d = __ldg(ei + E + w);
    float4 v = ((const float4*)x)[(long long)s * 32 + lane];
    const float* p = agg + (long long)d * D + lane * 4;
    asm volatile("red.global.add.v4.f32 [%0], {%1,%2,%3,%4};"
                 :: "l"(p), "f"(v.x), "f"(v.y), "f"(v.z), "f"(v.w)
                 : "memory");
}

// ---------------------------------------------------------------------------
// Tensor-core GEMM (tf32 HMMA, fp32 accumulate).
// out[r][c] = act( sum_k in[r][k] * Wt[k][c] + bias[c] )
// Block tile 128x128, full K=128 panel in smem, 8 warps, warp tile 32x64
// (2 x 8 grid of m16n8k8 fragments).
#define XSTR 132   // Xs pad: A-frag LDS bank = (gi*4+ti) -> conflict-free
#define WSTR 136   // Ws pad: B-frag LDS bank = (ti*8+gi) -> conflict-free

__device__ __forceinline__ float to_tf32(float x) {
    unsigned u;
    asm("cvt.rna.tf32.f32 %0, %1;" : "=r"(u) : "f"(x));
    return __uint_as_float(u);
}

__device__ __forceinline__ void mma_16x8x8(float* d, const float* a, const float* b) {
    asm volatile(
        "mma.sync.aligned.m16n8k8.row.col.f32.tf32.tf32.f32 "
        "{%0,%1,%2,%3}, {%4,%5,%6,%7}, {%8,%9}, {%0,%1,%2,%3};"
        : "+f"(d[0]), "+f"(d[1]), "+f"(d[2]), "+f"(d[3])
        : "r"(__float_as_uint(a[0])), "r"(__float_as_uint(a[1])),
          "r"(__float_as_uint(a[2])), "r"(__float_as_uint(a[3])),
          "r"(__float_as_uint(b[0])), "r"(__float_as_uint(b[1])));
}

__global__ __launch_bounds__(256, 1)
void gemm_tc_kernel(const float* __restrict__ in,
                    const float* __restrict__ wt,    // [k][c] 128x128
                    const float* __restrict__ bias,
                    float* __restrict__ out,
                    int nrows, int relu) {
    extern __shared__ float sm[];
    float* Xs = sm;                 // [128][XSTR]
    float* Ws = sm + 128 * XSTR;    // [128][WSTR]

    int tid = threadIdx.x;
    int row0 = blockIdx.x * 128;

    // Load X tile, convert to tf32 (RNA) once at load.
    for (int i = tid; i < 128 * 32; i += 256) {
        int r = i >> 5, kq = i & 31;
        float4 v = make_float4(0.f, 0.f, 0.f, 0.f);
        if (row0 + r < nrows)
            v = ((const float4*)in)[(long long)(row0 + r) * 32 + kq];
        v.x = to_tf32(v.x); v.y = to_tf32(v.y);
        v.z = to_tf32(v.z); v.w = to_tf32(v.w);
        *(float4*)(Xs + r * XSTR + kq * 4) = v;
    }
    // Load W tile (transposed in gmem), convert to tf32.
    for (int i = tid; i < 128 * 32; i += 256) {
        int k = i >> 5, cq = i & 31;
        float4 v = ((const float4*)wt)[i];
        v.x = to_tf32(v.x); v.y = to_tf32(v.y);
        v.z = to_tf32(v.z); v.w = to_tf32(v.w);
        *(float4*)(Ws + k * WSTR + cq * 4) = v;
    }
    __syncthreads();

    int warp = tid >> 5, lane = tid & 31;
    int gi = lane >> 2;        // groupID (0..7)
    int ti = lane & 3;         // thread-in-group (0..3)
    int mbase = (warp & 3) * 32;
    int nbase = (warp >> 2) * 64;

    float acc[2][8][4];
#pragma unroll
    for (int i = 0; i < 2; i++)
#pragma unroll
        for (int j = 0; j < 8; j++)
#pragma unroll
            for (int q = 0; q < 4; q++) acc[i][j][q] = 0.f;

#pragma unroll
    for (int kk = 0; kk < 16; kk++) {
        int k0 = kk * 8;
        float a[2][4];
#pragma unroll
        for (int i = 0; i < 2; i++) {
            int r = mbase + i * 16 + gi;
            a[i][0] = Xs[r * XSTR + k0 + ti];
            a[i][1] = Xs[(r + 8) * XSTR + k0 + ti];
            a[i][2] = Xs[r * XSTR + k0 + ti + 4];
            a[i][3] = Xs[(r + 8) * XSTR + k0 + ti + 4];
        }
        float b[8][2];
#pragma unroll
        for (int j = 0; j < 8; j++) {
            int c = nbase + j * 8 + gi;
            b[j][0] = Ws[(k0 + ti) * WSTR + c];
            b[j][1] = Ws[(k0 + ti + 4) * WSTR + c];
        }
#pragma unroll
        for (int i = 0; i < 2; i++)
#pragma unroll
            for (int j = 0; j < 8; j++)
                mma_16x8x8(acc[i][j], a[i], b[j]);
    }

    // Epilogue: bias + optional relu, float2 stores per fragment row.
#pragma unroll
    for (int j = 0; j < 8; j++) {
        int c0 = nbase + j * 8 + 2 * ti;
        float bx = __ldg(bias + c0);
        float by = __ldg(bias + c0 + 1);
#pragma unroll
        for (int i = 0; i < 2; i++) {
            int r0 = row0 + mbase + i * 16 + gi;
            float v0 = acc[i][j][0] + bx;
            float v1 = acc[i][j][1] + by;
            float v2 = acc[i][j][2] + bx;
            float v3 = acc[i][j][3] + by;
            if (relu) {
                v0 = fmaxf(v0, 0.f); v1 = fmaxf(v1, 0.f);
                v2 = fmaxf(v2, 0.f); v3 = fmaxf(v3, 0.f);
            }
            if (r0 < nrows)
                *(float2*)(out + (long long)r0 * D + c0) = make_float2(v0, v1);
            if (r0 + 8 < nrows)
                *(float2*)(out + (long long)(r0 + 8) * D + c0) = make_float2(v2, v3);
        }
    }
}

// ---------------------------------------------------------------------------
extern "C" void kernel_launch(void* const* d_in, const int* in_sizes, int n_in,
                              void* d_out, int out_size) {
    const float* x   = (const float*)d_in[0];
    const int*   ei  = (const int*)d_in[1];
    const float* w0a = (const float*)d_in[2];
    const float* b0a = (const float*)d_in[3];
    const float* w0b = (const float*)d_in[4];
    const float* b0b = (const float*)d_in[5];
    const float* w1a = (const float*)d_in[6];
    const float* b1a = (const float*)d_in[7];
    const float* w1b = (const float*)d_in[8];
    const float* b1b = (const float*)d_in[9];

    int N = in_sizes[0] / D;
    int E = in_sizes[1] / 2;

    float *p_h, *p_t, *p_o, *p_wt;
    cudaGetSymbolAddress((void**)&p_h,  g_h);
    cudaGetSymbolAddress((void**)&p_t,  g_t);
    cudaGetSymbolAddress((void**)&p_o,  g_o);
    cudaGetSymbolAddress((void**)&p_wt, g_wt);

    const int smem = (128 * XSTR + 128 * WSTR) * (int)sizeof(float);
    cudaFuncSetAttribute(gemm_tc_kernel, cudaFuncAttributeMaxDynamicSharedMemorySize, smem);

    int n4 = N * (D / 4);
    int copyBlocks = (n4 + 255) / 256;
    int scatBlocks = (E + 7) / 8;
    int gemmBlocks = (N + 127) / 128;

    transpose_w_kernel<<<(4 * D * D + 255) / 256, 256>>>(w0a, w0b, w1a, w1b);

    // ---- Layer 1 ----
    copy_kernel<<<copyBlocks, 256>>>(x, p_h, n4);
    scatter_kernel<<<scatBlocks, 256>>>(x, ei, p_h, E);
    gemm_tc_kernel<<<gemmBlocks, 256, smem>>>(p_h, p_wt + 0 * D * D, b0a, p_t, N, 1);
    gemm_tc_kernel<<<gemmBlocks, 256, smem>>>(p_t, p_wt + 1 * D * D, b0b, p_o, N, 0);

    // ---- Layer 2 ----
    copy_kernel<<<copyBlocks, 256>>>(p_o, p_h, n4);
    scatter_kernel<<<scatBlocks, 256>>>(p_o, ei, p_h, E);
    gemm_tc_kernel<<<gemmBlocks, 256, smem>>>(p_h, p_wt + 2 * D * D, b1a, p_t, N, 1);
    gemm_tc_kernel<<<gemmBlocks, 256, smem>>>(p_t, p_wt + 3 * D * D, b1b, (float*)d_out, N, 0);
}

// round 4
// speedup vs baseline: 2.9135x; 2.2833x over previous
#include <cuda_runtime.h>
#include <cstdint>

#define D 128
#define MAXN 100000
#define MAXE 1600000

// Scratch (allocation-free rule: __device__ globals)
__device__ __align__(16) float g_h[(size_t)MAXN * D];
__device__ __align__(16) float g_t[(size_t)MAXN * D];
__device__ __align__(16) float g_o[(size_t)MAXN * D];
__device__ __align__(16) float g_wt[4][D * D];
__device__ int g_deg[MAXN];
__device__ int g_incl[MAXN];
__device__ int g_bsum[128];
__device__ int g_boff[128];
__device__ int g_rowptr[MAXN + 1];
__device__ int g_cursor[MAXN];
__device__ int g_elist[MAXE];

// ---------------------------------------------------------------------------
__global__ void transpose_w_kernel(const float* __restrict__ w0,
                                   const float* __restrict__ w1,
                                   const float* __restrict__ w2,
                                   const float* __restrict__ w3) {
    int i = blockIdx.x * blockDim.x + threadIdx.x;
    if (i >= 4 * D * D) return;
    int widx = i >> 14;
    int k = (i >> 7) & 127;
    int c = i & 127;
    const float* w = (widx == 0) ? w0 : (widx == 1) ? w1 : (widx == 2) ? w2 : w3;
    g_wt[widx][k * D + c] = w[c * D + k];
}

// ---------------------------------------------------------------------------
// CSR build: histogram -> 2-level exclusive scan -> fill
__global__ void zero_deg_kernel(int n) {
    int i = blockIdx.x * blockDim.x + threadIdx.x;
    if (i < n) g_deg[i] = 0;
}

__global__ void hist_kernel(const int* __restrict__ ei, int E) {
    int e = blockIdx.x * blockDim.x + threadIdx.x;
    if (e < E) atomicAdd(&g_deg[__ldg(ei + E + e)], 1);
}

__global__ void scan1_kernel(int n) {       // per-block inclusive scan of deg
    __shared__ int s[1024];
    int t = threadIdx.x, b = blockIdx.x;
    int i = b * 1024 + t;
    int v = (i < n) ? g_deg[i] : 0;
    s[t] = v;
    __syncthreads();
#pragma unroll
    for (int off = 1; off < 1024; off <<= 1) {
        int u = (t >= off) ? s[t - off] : 0;
        __syncthreads();
        s[t] += u;
        __syncthreads();
    }
    if (i < n) g_incl[i] = s[t];
    if (t == 1023) g_bsum[b] = s[t];
}

__global__ void scan2_kernel(int nb) {      // exclusive scan of block sums (nb<=128)
    __shared__ int s[128];
    int t = threadIdx.x;
    int v = (t < nb) ? g_bsum[t] : 0;
    s[t] = v;
    __syncthreads();
#pragma unroll
    for (int off = 1; off < 128; off <<= 1) {
        int u = (t >= off) ? s[t - off] : 0;
        __syncthreads();
        s[t] += u;
        __syncthreads();
    }
    g_boff[t] = s[t] - v;
}

__global__ void scan3_kernel(int n, int E) {  // rowptr/cursor = global exclusive scan
    int i = blockIdx.x * blockDim.x + threadIdx.x;
    if (i < n) {
        int excl = g_boff[i >> 10] + g_incl[i] - g_deg[i];
        g_rowptr[i] = excl;
        g_cursor[i] = excl;
    }
    if (i == 0) g_rowptr[n] = E;
}

__global__ void fill_kernel(const int* __restrict__ ei, int E) {
    int e = blockIdx.x * blockDim.x + threadIdx.x;
    if (e >= E) return;
    int s = __ldg(ei + e);
    int d = __ldg(ei + E + e);
    int pos = atomicAdd(&g_cursor[d], 1);
    g_elist[pos] = s;
}

// ---------------------------------------------------------------------------
// Gather: h[n] = x[n] + sum_{s in N(n)} x[s].  One warp per node, unroll 4.
__global__ void gather_kernel(const float* __restrict__ x,
                              float* __restrict__ h, int N) {
    int w = (int)((blockIdx.x * (unsigned)blockDim.x + threadIdx.x) >> 5);
    if (w >= N) return;
    int lane = threadIdx.x & 31;
    const float4* x4 = (const float4*)x;
    float4 acc = __ldg(x4 + w * 32 + lane);
    int beg = __ldg(g_rowptr + w);
    int end = __ldg(g_rowptr + w + 1);
    int i = beg;
    for (; i + 4 <= end; i += 4) {
        int s0 = __ldg(g_elist + i);
        int s1 = __ldg(g_elist + i + 1);
        int s2 = __ldg(g_elist + i + 2);
        int s3 = __ldg(g_elist + i + 3);
        float4 v0 = __ldg(x4 + s0 * 32 + lane);
        float4 v1 = __ldg(x4 + s1 * 32 + lane);
        float4 v2 = __ldg(x4 + s2 * 32 + lane);
        float4 v3 = __ldg(x4 + s3 * 32 + lane);
        acc.x += (v0.x + v1.x) + (v2.x + v3.x);
        acc.y += (v0.y + v1.y) + (v2.y + v3.y);
        acc.z += (v0.z + v1.z) + (v2.z + v3.z);
        acc.w += (v0.w + v1.w) + (v2.w + v3.w);
    }
    for (; i < end; i++) {
        int s0 = __ldg(g_elist + i);
        float4 v0 = __ldg(x4 + s0 * 32 + lane);
        acc.x += v0.x; acc.y += v0.y; acc.z += v0.z; acc.w += v0.w;
    }
    ((float4*)h)[w * 32 + lane] = acc;
}

// ---------------------------------------------------------------------------
// Persistent tensor-core GEMM (tf32 HMMA, fp32 acc).
// W panel (128x128) in smem once per block; X streamed in 64-row tiles,
// double-buffered (LDG->regs overlaps MMA).
#define XSTR 132
#define WSTR 136
#define TROWS 64

__device__ __forceinline__ float to_tf32(float x) {
    unsigned u;
    asm("cvt.rna.tf32.f32 %0, %1;" : "=r"(u) : "f"(x));
    return __uint_as_float(u);
}

__device__ __forceinline__ void mma_16x8x8(float* d, const float* a, const float* b) {
    asm volatile(
        "mma.sync.aligned.m16n8k8.row.col.f32.tf32.tf32.f32 "
        "{%0,%1,%2,%3}, {%4,%5,%6,%7}, {%8,%9}, {%0,%1,%2,%3};"
        : "+f"(d[0]), "+f"(d[1]), "+f"(d[2]), "+f"(d[3])
        : "r"(__float_as_uint(a[0])), "r"(__float_as_uint(a[1])),
          "r"(__float_as_uint(a[2])), "r"(__float_as_uint(a[3])),
          "r"(__float_as_uint(b[0])), "r"(__float_as_uint(b[1])));
}

__global__ __launch_bounds__(256, 1)
void gemm_tc_kernel(const float* __restrict__ in,
                    const float* __restrict__ wt,
                    const float* __restrict__ bias,
                    float* __restrict__ out,
                    int nrows, int relu) {
    extern __shared__ float sm[];
    float* Xs0 = sm;                          // [64][XSTR]
    float* Xs1 = sm + TROWS * XSTR;
    float* Ws  = sm + 2 * TROWS * XSTR;       // [128][WSTR]

    int tid = threadIdx.x;

    // Load W panel once (tf32)
    for (int i = tid; i < 128 * 32; i += 256) {
        int k = i >> 5, cq = i & 31;
        float4 v = ((const float4*)wt)[i];
        v.x = to_tf32(v.x); v.y = to_tf32(v.y);
        v.z = to_tf32(v.z); v.w = to_tf32(v.w);
        *(float4*)(Ws + k * WSTR + cq * 4) = v;
    }

    int warp = tid >> 5, lane = tid & 31;
    int gi = lane >> 2, ti = lane & 3;
    int mbase = (warp & 3) * 16;
    int nbase = (warp >> 2) * 64;

    // Hoist bias (constant across tiles)
    float bxv[8], byv[8];
#pragma unroll
    for (int j = 0; j < 8; j++) {
        int c0 = nbase + j * 8 + 2 * ti;
        bxv[j] = __ldg(bias + c0);
        byv[j] = __ldg(bias + c0 + 1);
    }

    int ntiles = (nrows + TROWS - 1) / TROWS;
    int stride = gridDim.x;

    float4 reg[8];
    int r_ld = tid >> 5;        // row within tile (per pass p: r_ld + 8*p)
    int kq_ld = tid & 31;

    // prologue: load + store tile blockIdx.x into Xs0
    {
        long long r0 = (long long)blockIdx.x * TROWS;
#pragma unroll
        for (int p = 0; p < 8; p++) {
            long long gr = r0 + r_ld + 8 * p;
            reg[p] = (gr < nrows) ? __ldg((const float4*)in + gr * 32 + kq_ld)
                                  : make_float4(0.f, 0.f, 0.f, 0.f);
        }
#pragma unroll
        for (int p = 0; p < 8; p++) {
            float4 v = reg[p];
            v.x = to_tf32(v.x); v.y = to_tf32(v.y);
            v.z = to_tf32(v.z); v.w = to_tf32(v.w);
            *(float4*)(Xs0 + (r_ld + 8 * p) * XSTR + kq_ld * 4) = v;
        }
    }
    __syncthreads();

    float* bufs[2] = {Xs0, Xs1};
    int buf = 0;

    for (int tt = blockIdx.x; tt < ntiles; tt += stride) {
        int nxt = tt + stride;
        // prefetch next tile into registers (overlaps MMA below)
        if (nxt < ntiles) {
            long long r0 = (long long)nxt * TROWS;
#pragma unroll
            for (int p = 0; p < 8; p++) {
                long long gr = r0 + r_ld + 8 * p;
                reg[p] = (gr < nrows) ? __ldg((const float4*)in + gr * 32 + kq_ld)
                                      : make_float4(0.f, 0.f, 0.f, 0.f);
            }
        }

        const float* Xs = bufs[buf];
        float acc[8][4];
#pragma unroll
        for (int j = 0; j < 8; j++)
#pragma unroll
            for (int q = 0; q < 4; q++) acc[j][q] = 0.f;

#pragma unroll
        for (int kk = 0; kk < 16; kk++) {
            int k0 = kk * 8;
            float a[4];
            int r = mbase + gi;
            a[0] = Xs[r * XSTR + k0 + ti];
            a[1] = Xs[(r + 8) * XSTR + k0 + ti];
            a[2] = Xs[r * XSTR + k0 + ti + 4];
            a[3] = Xs[(r + 8) * XSTR + k0 + ti + 4];
#pragma unroll
            for (int j = 0; j < 8; j++) {
                float b[2];
                int c = nbase + j * 8 + gi;
                b[0] = Ws[(k0 + ti) * WSTR + c];
                b[1] = Ws[(k0 + ti + 4) * WSTR + c];
                mma_16x8x8(acc[j], a, b);
            }
        }

        // epilogue
        long long row0 = (long long)tt * TROWS + mbase + gi;
#pragma unroll
        for (int j = 0; j < 8; j++) {
            int c0 = nbase + j * 8 + 2 * ti;
            float v0 = acc[j][0] + bxv[j];
            float v1 = acc[j][1] + byv[j];
            float v2 = acc[j][2] + bxv[j];
            float v3 = acc[j][3] + byv[j];
            if (relu) {
                v0 = fmaxf(v0, 0.f); v1 = fmaxf(v1, 0.f);
                v2 = fmaxf(v2, 0.f); v3 = fmaxf(v3, 0.f);
            }
            if (row0 < nrows)
                *(float2*)(out + row0 * D + c0) = make_float2(v0, v1);
            if (row0 + 8 < nrows)
                *(float2*)(out + (row0 + 8) * D + c0) = make_float2(v2, v3);
        }

        // stage prefetched tile into the other buffer
        if (nxt < ntiles) {
#pragma unroll
            for (int p = 0; p < 8; p++) {
                float4 v = reg[p];
                v.x = to_tf32(v.x); v.y = to_tf32(v.y);
                v.z = to_tf32(v.z); v.w = to_tf32(v.w);
                *(float4*)(bufs[buf ^ 1] + (r_ld + 8 * p) * XSTR + kq_ld * 4) = v;
            }
            __syncthreads();
            buf ^= 1;
        }
    }
}

// ---------------------------------------------------------------------------
extern "C" void kernel_launch(void* const* d_in, const int* in_sizes, int n_in,
                              void* d_out, int out_size) {
    const float* x   = (const float*)d_in[0];
    const int*   ei  = (const int*)d_in[1];
    const float* w0a = (const float*)d_in[2];
    const float* b0a = (const float*)d_in[3];
    const float* w0b = (const float*)d_in[4];
    const float* b0b = (const float*)d_in[5];
    const float* w1a = (const float*)d_in[6];
    const float* b1a = (const float*)d_in[7];
    const float* w1b = (const float*)d_in[8];
    const float* b1b = (const float*)d_in[9];

    int N = in_sizes[0] / D;
    int E = in_sizes[1] / 2;

    float *p_h, *p_t, *p_o, *p_wt;
    cudaGetSymbolAddress((void**)&p_h,  g_h);
    cudaGetSymbolAddress((void**)&p_t,  g_t);
    cudaGetSymbolAddress((void**)&p_o,  g_o);
    cudaGetSymbolAddress((void**)&p_wt, g_wt);

    int nsm = 148;
    cudaDeviceGetAttribute(&nsm, cudaDevAttrMultiProcessorCount, 0);

    const int smem = (2 * TROWS * XSTR + 128 * WSTR) * (int)sizeof(float);
    cudaFuncSetAttribute(gemm_tc_kernel, cudaFuncAttributeMaxDynamicSharedMemorySize, smem);

    int nb = (N + 1023) / 1024;
    int gatherBlocks = (N + 7) / 8;   // 8 warps (nodes) per 256-thread block

    transpose_w_kernel<<<(4 * D * D + 255) / 256, 256>>>(w0a, w0b, w1a, w1b);

    // ---- CSR build (per launch; graph-capturable, deterministic work) ----
    zero_deg_kernel<<<(N + 255) / 256, 256>>>(N);
    hist_kernel<<<(E + 255) / 256, 256>>>(ei, E);
    scan1_kernel<<<nb, 1024>>>(N);
    scan2_kernel<<<1, 128>>>(nb);
    scan3_kernel<<<(N + 255) / 256, 256>>>(N, E);
    fill_kernel<<<(E + 255) / 256, 256>>>(ei, E);

    // ---- Layer 1 ----
    gather_kernel<<<gatherBlocks, 256>>>(x, p_h, N);
    gemm_tc_kernel<<<nsm, 256, smem>>>(p_h, p_wt + 0 * D * D, b0a, p_t, N, 1);
    gemm_tc_kernel<<<nsm, 256, smem>>>(p_t, p_wt + 1 * D * D, b0b, p_o, N, 0);

    // ---- Layer 2 ----
    gather_kernel<<<gatherBlocks, 256>>>(p_o, p_h, N);
    gemm_tc_kernel<<<nsm, 256, smem>>>(p_h, p_wt + 2 * D * D, b1a, p_t, N, 1);
    gemm_tc_kernel<<<nsm, 256, smem>>>(p_t, p_wt + 3 * D * D, b1b, (float*)d_out, N, 0);
}

// round 5
// speedup vs baseline: 4.1104x; 1.4108x over previous
#include <cuda_runtime.h>
#include <cuda_fp16.h>
#include <cstdint>

#define D 128
#define MAXN 100000
#define MAXE 1600000

// Scratch (allocation-free rule: __device__ globals) — fp16 activations
__device__ __align__(16) __half g_xh[(size_t)MAXN * D];
__device__ __align__(16) __half g_hh[(size_t)MAXN * D];
__device__ __align__(16) __half g_th[(size_t)MAXN * D];
__device__ __align__(16) __half g_oh[(size_t)MAXN * D];
__device__ __align__(16) __half g_wh[4 * D * D];   // weights [c][k] (original layout), fp16
__device__ int g_deg[MAXN];
__device__ int g_incl[MAXN];
__device__ int g_bsum[128];
__device__ int g_boff[128];
__device__ int g_rowptr[MAXN + 1];
__device__ int g_cursor[MAXN];
__device__ int g_elist[MAXE];

// ---------------------------------------------------------------------------
// Convert weights fp32 -> fp16, same [c][k] layout (this IS the mma .col B layout)
__global__ void convert_w_kernel(const float* __restrict__ w0,
                                 const float* __restrict__ w1,
                                 const float* __restrict__ w2,
                                 const float* __restrict__ w3) {
    int i = blockIdx.x * blockDim.x + threadIdx.x;
    if (i >= 4 * D * D) return;
    int widx = i >> 14;
    const float* w = (widx == 0) ? w0 : (widx == 1) ? w1 : (widx == 2) ? w2 : w3;
    g_wh[i] = __float2half(w[i & 16383]);
}

// Convert x fp32 -> fp16
__global__ void convert_x_kernel(const float* __restrict__ x, int n4) {
    int i = blockIdx.x * blockDim.x + threadIdx.x;   // one float4 -> one uint2
    if (i >= n4) return;
    float4 v = __ldg((const float4*)x + i);
    __half2 h0 = __floats2half2_rn(v.x, v.y);
    __half2 h1 = __floats2half2_rn(v.z, v.w);
    uint2 u;
    u.x = *(unsigned*)&h0;
    u.y = *(unsigned*)&h1;
    ((uint2*)g_xh)[i] = u;
}

// ---------------------------------------------------------------------------
// CSR build: histogram -> 2-level exclusive scan -> fill
__global__ void zero_deg_kernel(int n) {
    int i = blockIdx.x * blockDim.x + threadIdx.x;
    if (i < n) g_deg[i] = 0;
}

__global__ void hist_kernel(const int* __restrict__ ei, int E) {
    int e = blockIdx.x * blockDim.x + threadIdx.x;
    if (e < E) atomicAdd(&g_deg[__ldg(ei + E + e)], 1);
}

__global__ void scan1_kernel(int n) {
    __shared__ int s[1024];
    int t = threadIdx.x, b = blockIdx.x;
    int i = b * 1024 + t;
    int v = (i < n) ? g_deg[i] : 0;
    s[t] = v;
    __syncthreads();
#pragma unroll
    for (int off = 1; off < 1024; off <<= 1) {
        int u = (t >= off) ? s[t - off] : 0;
        __syncthreads();
        s[t] += u;
        __syncthreads();
    }
    if (i < n) g_incl[i] = s[t];
    if (t == 1023) g_bsum[b] = s[t];
}

__global__ void scan2_kernel(int nb) {
    __shared__ int s[128];
    int t = threadIdx.x;
    int v = (t < nb) ? g_bsum[t] : 0;
    s[t] = v;
    __syncthreads();
#pragma unroll
    for (int off = 1; off < 128; off <<= 1) {
        int u = (t >= off) ? s[t - off] : 0;
        __syncthreads();
        s[t] += u;
        __syncthreads();
    }
    g_boff[t] = s[t] - v;
}

__global__ void scan3_kernel(int n, int E) {
    int i = blockIdx.x * blockDim.x + threadIdx.x;
    if (i < n) {
        int excl = g_boff[i >> 10] + g_incl[i] - g_deg[i];
        g_rowptr[i] = excl;
        g_cursor[i] = excl;
    }
    if (i == 0) g_rowptr[n] = E;
}

__global__ void fill_kernel(const int* __restrict__ ei, int E) {
    int e = blockIdx.x * blockDim.x + threadIdx.x;
    if (e >= E) return;
    int s = __ldg(ei + e);
    int d = __ldg(ei + E + e);
    int pos = atomicAdd(&g_cursor[d], 1);
    g_elist[pos] = s;
}

// ---------------------------------------------------------------------------
// Gather (fp16 in, fp32 accumulate, fp16 out): h[n] = x[n] + sum_{s in N(n)} x[s]
// One warp per node; lane handles 4 features (uint2 = 4 halves). Unroll 4.
__device__ __forceinline__ void acc_add(float4& a, uint2 u) {
    float2 f0 = __half22float2(*(__half2*)&u.x);
    float2 f1 = __half22float2(*(__half2*)&u.y);
    a.x += f0.x; a.y += f0.y; a.z += f1.x; a.w += f1.y;
}

__global__ void gather_h_kernel(const __half* __restrict__ xin,
                                __half* __restrict__ hout, int N) {
    int w = (int)((blockIdx.x * (unsigned)blockDim.x + threadIdx.x) >> 5);
    if (w >= N) return;
    int lane = threadIdx.x & 31;
    const uint2* x2 = (const uint2*)xin;   // 32 uint2 per row
    float4 acc = make_float4(0.f, 0.f, 0.f, 0.f);
    acc_add(acc, __ldg(x2 + (long long)w * 32 + lane));
    int beg = __ldg(g_rowptr + w);
    int end = __ldg(g_rowptr + w + 1);
    int i = beg;
    for (; i + 4 <= end; i += 4) {
        int s0 = __ldg(g_elist + i);
        int s1 = __ldg(g_elist + i + 1);
        int s2 = __ldg(g_elist + i + 2);
        int s3 = __ldg(g_elist + i + 3);
        uint2 v0 = __ldg(x2 + (long long)s0 * 32 + lane);
        uint2 v1 = __ldg(x2 + (long long)s1 * 32 + lane);
        uint2 v2 = __ldg(x2 + (long long)s2 * 32 + lane);
        uint2 v3 = __ldg(x2 + (long long)s3 * 32 + lane);
        acc_add(acc, v0); acc_add(acc, v1); acc_add(acc, v2); acc_add(acc, v3);
    }
    for (; i < end; i++) {
        int s0 = __ldg(g_elist + i);
        acc_add(acc, __ldg(x2 + (long long)s0 * 32 + lane));
    }
    __half2 h0 = __floats2half2_rn(acc.x, acc.y);
    __half2 h1 = __floats2half2_rn(acc.z, acc.w);
    uint2 u;
    u.x = *(unsigned*)&h0;
    u.y = *(unsigned*)&h1;
    ((uint2*)hout)[(long long)w * 32 + lane] = u;
}

// ---------------------------------------------------------------------------
// Persistent fp16 tensor-core GEMM (m16n8k16, fp32 accumulate).
// out[r][c] = act( sum_k in[r][k] * W[c][k] + bias[c] )
// W panel (128x128 halves) in smem once; X in 64-row tiles, double-buffered.
#define XSTR 136   // halves; /2=68 ≡ 4 (mod 32) -> A-frag bank = 4*gi+ti, conflict-free
#define WSTR 136   // same for B-frags
#define TROWS 64

__device__ __forceinline__ void mma_16x8x16(float* d, const unsigned* a, const unsigned* b) {
    asm volatile(
        "mma.sync.aligned.m16n8k16.row.col.f32.f16.f16.f32 "
        "{%0,%1,%2,%3}, {%4,%5,%6,%7}, {%8,%9}, {%0,%1,%2,%3};"
        : "+f"(d[0]), "+f"(d[1]), "+f"(d[2]), "+f"(d[3])
        : "r"(a[0]), "r"(a[1]), "r"(a[2]), "r"(a[3]), "r"(b[0]), "r"(b[1]));
}

__global__ __launch_bounds__(256, 2)
void gemm_fp16_kernel(const __half* __restrict__ in,
                      const __half* __restrict__ w,     // [c][k] halves
                      const float* __restrict__ bias,
                      __half* __restrict__ outh,        // fp16 out (if non-null)
                      float* __restrict__ outf,         // fp32 out (if non-null)
                      int nrows, int relu) {
    extern __shared__ __half smh[];
    __half* Xs0 = smh;                         // [64][XSTR]
    __half* Xs1 = smh + TROWS * XSTR;
    __half* Ws  = smh + 2 * TROWS * XSTR;      // [128][WSTR]

    int tid = threadIdx.x;

    // Load W panel once: 128 rows x 16 uint4 (coalesced, conflict-free stores)
    for (int i = tid; i < 128 * 16; i += 256) {
        int c = i >> 4, seg = i & 15;
        uint4 v = __ldg((const uint4*)w + i);
        *(uint4*)(Ws + c * WSTR + seg * 8) = v;
    }

    int warp = tid >> 5, lane = tid & 31;
    int gi = lane >> 2, ti = lane & 3;
    int mbase = (warp & 3) * 16;
    int nbase = (warp >> 2) * 64;

    // Hoist bias
    float bxv[8], byv[8];
#pragma unroll
    for (int j = 0; j < 8; j++) {
        int c0 = nbase + j * 8 + 2 * ti;
        bxv[j] = __ldg(bias + c0);
        byv[j] = __ldg(bias + c0 + 1);
    }

    int ntiles = (nrows + TROWS - 1) / TROWS;
    int stride = gridDim.x;

    uint4 reg[4];

    // prologue: load tile blockIdx.x into Xs0 (1024 uint4, 4 per thread)
    {
        long long r0 = (long long)blockIdx.x * TROWS;
#pragma unroll
        for (int p = 0; p < 4; p++) {
            int idx = tid + 256 * p;
            long long gr = r0 + (idx >> 4);
            reg[p] = (gr < nrows) ? __ldg((const uint4*)in + gr * 16 + (idx & 15))
                                  : make_uint4(0, 0, 0, 0);
        }
#pragma unroll
        for (int p = 0; p < 4; p++) {
            int idx = tid + 256 * p;
            *(uint4*)(Xs0 + (idx >> 4) * XSTR + (idx & 15) * 8) = reg[p];
        }
    }
    __syncthreads();

    __half* bufs[2] = {Xs0, Xs1};
    int buf = 0;

    for (int tt = blockIdx.x; tt < ntiles; tt += stride) {
        int nxt = tt + stride;
        if (nxt < ntiles) {
            long long r0 = (long long)nxt * TROWS;
#pragma unroll
            for (int p = 0; p < 4; p++) {
                int idx = tid + 256 * p;
                long long gr = r0 + (idx >> 4);
                reg[p] = (gr < nrows) ? __ldg((const uint4*)in + gr * 16 + (idx & 15))
                                      : make_uint4(0, 0, 0, 0);
            }
        }

        const __half* Xs = bufs[buf];
        float acc[8][4];
#pragma unroll
        for (int j = 0; j < 8; j++)
#pragma unroll
            for (int q = 0; q < 4; q++) acc[j][q] = 0.f;

#pragma unroll
        for (int kk = 0; kk < 8; kk++) {
            int k0 = kk * 16;
            unsigned a[4];
            int r = mbase + gi;
            a[0] = *(const unsigned*)(Xs + r * XSTR + k0 + 2 * ti);
            a[1] = *(const unsigned*)(Xs + (r + 8) * XSTR + k0 + 2 * ti);
            a[2] = *(const unsigned*)(Xs + r * XSTR + k0 + 2 * ti + 8);
            a[3] = *(const unsigned*)(Xs + (r + 8) * XSTR + k0 + 2 * ti + 8);
#pragma unroll
            for (int j = 0; j < 8; j++) {
                int c = nbase + j * 8 + gi;
                unsigned b[2];
                b[0] = *(const unsigned*)(Ws + c * WSTR + k0 + 2 * ti);
                b[1] = *(const unsigned*)(Ws + c * WSTR + k0 + 2 * ti + 8);
                mma_16x8x16(acc[j], a, b);
            }
        }

        // epilogue
        long long row0 = (long long)tt * TROWS + mbase + gi;
#pragma unroll
        for (int j = 0; j < 8; j++) {
            int c0 = nbase + j * 8 + 2 * ti;
            float v0 = acc[j][0] + bxv[j];
            float v1 = acc[j][1] + byv[j];
            float v2 = acc[j][2] + bxv[j];
            float v3 = acc[j][3] + byv[j];
            if (relu) {
                v0 = fmaxf(v0, 0.f); v1 = fmaxf(v1, 0.f);
                v2 = fmaxf(v2, 0.f); v3 = fmaxf(v3, 0.f);
            }
            if (outf) {
                if (row0 < nrows)
                    *(float2*)(outf + row0 * D + c0) = make_float2(v0, v1);
                if (row0 + 8 < nrows)
                    *(float2*)(outf + (row0 + 8) * D + c0) = make_float2(v2, v3);
            } else {
                if (row0 < nrows)
                    *(__half2*)(outh + row0 * D + c0) = __floats2half2_rn(v0, v1);
                if (row0 + 8 < nrows)
                    *(__half2*)(outh + (row0 + 8) * D + c0) = __floats2half2_rn(v2, v3);
            }
        }

        if (nxt < ntiles) {
#pragma unroll
            for (int p = 0; p < 4; p++) {
                int idx = tid + 256 * p;
                *(uint4*)(bufs[buf ^ 1] + (idx >> 4) * XSTR + (idx & 15) * 8) = reg[p];
            }
            __syncthreads();
            buf ^= 1;
        }
    }
}

// ---------------------------------------------------------------------------
extern "C" void kernel_launch(void* const* d_in, const int* in_sizes, int n_in,
                              void* d_out, int out_size) {
    const float* x   = (const float*)d_in[0];
    const int*   ei  = (const int*)d_in[1];
    const float* w0a = (const float*)d_in[2];
    const float* b0a = (const float*)d_in[3];
    const float* w0b = (const float*)d_in[4];
    const float* b0b = (const float*)d_in[5];
    const float* w1a = (const float*)d_in[6];
    const float* b1a = (const float*)d_in[7];
    const float* w1b = (const float*)d_in[8];
    const float* b1b = (const float*)d_in[9];

    int N = in_sizes[0] / D;
    int E = in_sizes[1] / 2;

    __half *p_xh, *p_hh, *p_th, *p_oh, *p_wh;
    cudaGetSymbolAddress((void**)&p_xh, g_xh);
    cudaGetSymbolAddress((void**)&p_hh, g_hh);
    cudaGetSymbolAddress((void**)&p_th, g_th);
    cudaGetSymbolAddress((void**)&p_oh, g_oh);
    cudaGetSymbolAddress((void**)&p_wh, g_wh);

    int nsm = 148;
    cudaDeviceGetAttribute(&nsm, cudaDevAttrMultiProcessorCount, 0);

    const int smem = (2 * TROWS * XSTR + 128 * WSTR) * (int)sizeof(__half);
    cudaFuncSetAttribute(gemm_fp16_kernel, cudaFuncAttributeMaxDynamicSharedMemorySize, smem);

    int nb = (N + 1023) / 1024;
    int gatherBlocks = (N + 7) / 8;
    int gemmGrid = 2 * nsm;
    int n4 = N * (D / 4);

    convert_w_kernel<<<(4 * D * D + 255) / 256, 256>>>(w0a, w0b, w1a, w1b);
    convert_x_kernel<<<(n4 + 255) / 256, 256>>>(x, n4);

    // ---- CSR build ----
    zero_deg_kernel<<<(N + 255) / 256, 256>>>(N);
    hist_kernel<<<(E + 255) / 256, 256>>>(ei, E);
    scan1_kernel<<<nb, 1024>>>(N);
    scan2_kernel<<<1, 128>>>(nb);
    scan3_kernel<<<(N + 255) / 256, 256>>>(N, E);
    fill_kernel<<<(E + 255) / 256, 256>>>(ei, E);

    // ---- Layer 1 ----
    gather_h_kernel<<<gatherBlocks, 256>>>(p_xh, p_hh, N);
    gemm_fp16_kernel<<<gemmGrid, 256, smem>>>(p_hh, p_wh + 0 * D * D, b0a, p_th, nullptr, N, 1);
    gemm_fp16_kernel<<<gemmGrid, 256, smem>>>(p_th, p_wh + 1 * D * D, b0b, p_oh, nullptr, N, 0);

    // ---- Layer 2 ----
    gather_h_kernel<<<gatherBlocks, 256>>>(p_oh, p_hh, N);
    gemm_fp16_kernel<<<gemmGrid, 256, smem>>>(p_hh, p_wh + 2 * D * D, b1a, p_th, nullptr, N, 1);
    gemm_fp16_kernel<<<gemmGrid, 256, smem>>>(p_th, p_wh + 3 * D * D, b1b, nullptr, (float*)d_out, N, 0);
}

// round 6
// speedup vs baseline: 4.2709x; 1.0391x over previous
#include <cuda_runtime.h>
#include <cuda_fp16.h>
#include <cstdint>

#define D 128
#define MAXN 100000
#define MAXE 1600000

// Scratch (allocation-free rule: __device__ globals) — fp16 activations
__device__ __align__(16) __half g_xh[(size_t)MAXN * D];
__device__ __align__(16) __half g_hh[(size_t)MAXN * D];
__device__ __align__(16) __half g_oh[(size_t)MAXN * D];
__device__ __align__(16) __half g_wh[4 * D * D];   // weights [c][k] fp16
__device__ int g_deg[MAXN];
__device__ int g_incl[MAXN];
__device__ int g_bsum[128];
__device__ int g_boff[128];
__device__ int g_rowptr[MAXN + 1];
__device__ int g_cursor[MAXN];
__device__ int g_elist[MAXE];

// ---------------------------------------------------------------------------
__global__ void convert_w_kernel(const float* __restrict__ w0,
                                 const float* __restrict__ w1,
                                 const float* __restrict__ w2,
                                 const float* __restrict__ w3) {
    int i = blockIdx.x * blockDim.x + threadIdx.x;
    if (i >= 4 * D * D) return;
    int widx = i >> 14;
    const float* w = (widx == 0) ? w0 : (widx == 1) ? w1 : (widx == 2) ? w2 : w3;
    g_wh[i] = __float2half(w[i & 16383]);
}

__global__ void convert_x_kernel(const float* __restrict__ x, int n4) {
    int i = blockIdx.x * blockDim.x + threadIdx.x;
    if (i >= n4) return;
    float4 v = __ldg((const float4*)x + i);
    __half2 h0 = __floats2half2_rn(v.x, v.y);
    __half2 h1 = __floats2half2_rn(v.z, v.w);
    uint2 u;
    u.x = *(unsigned*)&h0;
    u.y = *(unsigned*)&h1;
    ((uint2*)g_xh)[i] = u;
}

// ---------------------------------------------------------------------------
// CSR build
__global__ void zero_deg_kernel(int n) {
    int i = blockIdx.x * blockDim.x + threadIdx.x;
    if (i < n) g_deg[i] = 0;
}

// 4 edges per thread, int4 read of dst half
__global__ void hist_kernel(const int* __restrict__ ei, int E) {
    int t = blockIdx.x * blockDim.x + threadIdx.x;
    int base = t * 4;
    if (base + 4 <= E) {
        int4 d = __ldg((const int4*)(ei + E) + t);
        atomicAdd(&g_deg[d.x], 1);
        atomicAdd(&g_deg[d.y], 1);
        atomicAdd(&g_deg[d.z], 1);
        atomicAdd(&g_deg[d.w], 1);
    } else {
        for (int e = base; e < E; e++) atomicAdd(&g_deg[__ldg(ei + E + e)], 1);
    }
}

// Shfl-based block scan (1024 threads, 3 barriers)
__global__ void scan1_kernel(int n) {
    __shared__ int wsum[32];
    int t = threadIdx.x, b = blockIdx.x;
    int i = b * 1024 + t;
    int lane = t & 31, warp = t >> 5;
    int v = (i < n) ? g_deg[i] : 0;
    int s = v;
#pragma unroll
    for (int off = 1; off < 32; off <<= 1) {
        int u = __shfl_up_sync(0xffffffffu, s, off);
        if (lane >= off) s += u;
    }
    if (lane == 31) wsum[warp] = s;
    __syncthreads();
    if (warp == 0) {
        int ws = wsum[lane];
#pragma unroll
        for (int off = 1; off < 32; off <<= 1) {
            int u = __shfl_up_sync(0xffffffffu, ws, off);
            if (lane >= off) ws += u;
        }
        wsum[lane] = ws;
    }
    __syncthreads();
    int incl = s + (warp > 0 ? wsum[warp - 1] : 0);
    if (i < n) g_incl[i] = incl;
    if (t == 1023) g_bsum[b] = incl;
}

__global__ void scan2_kernel(int nb) {
    __shared__ int s[128];
    int t = threadIdx.x;
    int v = (t < nb) ? g_bsum[t] : 0;
    s[t] = v;
    __syncthreads();
#pragma unroll
    for (int off = 1; off < 128; off <<= 1) {
        int u = (t >= off) ? s[t - off] : 0;
        __syncthreads();
        s[t] += u;
        __syncthreads();
    }
    g_boff[t] = s[t] - v;
}

__global__ void scan3_kernel(int n, int E) {
    int i = blockIdx.x * blockDim.x + threadIdx.x;
    if (i < n) {
        int excl = g_boff[i >> 10] + g_incl[i] - g_deg[i];
        g_rowptr[i] = excl;
        g_cursor[i] = excl;
    }
    if (i == 0) g_rowptr[n] = E;
}

// 4 edges per thread, int4 reads of both halves
__global__ void fill_kernel(const int* __restrict__ ei, int E) {
    int t = blockIdx.x * blockDim.x + threadIdx.x;
    int base = t * 4;
    if (base + 4 <= E) {
        int4 s = __ldg((const int4*)ei + t);
        int4 d = __ldg((const int4*)(ei + E) + t);
        g_elist[atomicAdd(&g_cursor[d.x], 1)] = s.x;
        g_elist[atomicAdd(&g_cursor[d.y], 1)] = s.y;
        g_elist[atomicAdd(&g_cursor[d.z], 1)] = s.z;
        g_elist[atomicAdd(&g_cursor[d.w], 1)] = s.w;
    } else {
        for (int e = base; e < E; e++) {
            int s = __ldg(ei + e);
            int d = __ldg(ei + E + e);
            g_elist[atomicAdd(&g_cursor[d], 1)] = s;
        }
    }
}

// ---------------------------------------------------------------------------
// Gather: h[n] = x[n] + sum_{s in N(n)} x[s].  fp16 in/out, fp32 accumulate.
__device__ __forceinline__ void acc_add(float4& a, uint2 u) {
    float2 f0 = __half22float2(*(__half2*)&u.x);
    float2 f1 = __half22float2(*(__half2*)&u.y);
    a.x += f0.x; a.y += f0.y; a.z += f1.x; a.w += f1.y;
}

__global__ void gather_h_kernel(const __half* __restrict__ xin,
                                __half* __restrict__ hout, int N) {
    int w = (int)((blockIdx.x * (unsigned)blockDim.x + threadIdx.x) >> 5);
    if (w >= N) return;
    int lane = threadIdx.x & 31;
    const uint2* x2 = (const uint2*)xin;
    float4 acc = make_float4(0.f, 0.f, 0.f, 0.f);
    acc_add(acc, __ldg(x2 + (long long)w * 32 + lane));
    int beg = __ldg(g_rowptr + w);
    int end = __ldg(g_rowptr + w + 1);
    int i = beg;
    for (; i + 4 <= end; i += 4) {
        int s0 = __ldg(g_elist + i);
        int s1 = __ldg(g_elist + i + 1);
        int s2 = __ldg(g_elist + i + 2);
        int s3 = __ldg(g_elist + i + 3);
        uint2 v0 = __ldg(x2 + (long long)s0 * 32 + lane);
        uint2 v1 = __ldg(x2 + (long long)s1 * 32 + lane);
        uint2 v2 = __ldg(x2 + (long long)s2 * 32 + lane);
        uint2 v3 = __ldg(x2 + (long long)s3 * 32 + lane);
        acc_add(acc, v0); acc_add(acc, v1); acc_add(acc, v2); acc_add(acc, v3);
    }
    for (; i < end; i++) {
        int s0 = __ldg(g_elist + i);
        acc_add(acc, __ldg(x2 + (long long)s0 * 32 + lane));
    }
    __half2 h0 = __floats2half2_rn(acc.x, acc.y);
    __half2 h1 = __floats2half2_rn(acc.z, acc.w);
    uint2 u;
    u.x = *(unsigned*)&h0;
    u.y = *(unsigned*)&h1;
    ((uint2*)hout)[(long long)w * 32 + lane] = u;
}

// ---------------------------------------------------------------------------
// Fused layer: out = relu(X @ W1^T + b1) @ W2^T + b2   (persistent, fp16 MMA)
// Tile 128 rows; each warp owns a 16-row stripe, all 128 cols.
// T never leaves registers: C-fragment of MMA1 == A-fragment of MMA2.
#define XSTR 136
#define WSTR 136
#define TR 128

__device__ __forceinline__ void mma_16x8x16(float* d, const unsigned* a, const unsigned* b) {
    asm volatile(
        "mma.sync.aligned.m16n8k16.row.col.f32.f16.f16.f32 "
        "{%0,%1,%2,%3}, {%4,%5,%6,%7}, {%8,%9}, {%0,%1,%2,%3};"
        : "+f"(d[0]), "+f"(d[1]), "+f"(d[2]), "+f"(d[3])
        : "r"(a[0]), "r"(a[1]), "r"(a[2]), "r"(a[3]), "r"(b[0]), "r"(b[1]));
}

__global__ __launch_bounds__(256, 1)
void layer_fused_kernel(const __half* __restrict__ in,
                        const __half* __restrict__ w1,   // [c][k]
                        const float* __restrict__ b1,
                        const __half* __restrict__ w2,   // [c][k]
                        const float* __restrict__ b2,
                        __half* __restrict__ outh,
                        float* __restrict__ outf,
                        int nrows) {
    extern __shared__ __half smh[];
    __half* Ws1 = smh;                        // [128][WSTR]
    __half* Ws2 = smh + 128 * WSTR;           // [128][WSTR]
    __half* Xs0 = smh + 2 * 128 * WSTR;       // [128][XSTR]
    __half* Xs1 = Xs0 + TR * XSTR;

    int tid = threadIdx.x;

    // Load both W panels (each 128 rows x 16 uint4)
    for (int i = tid; i < 128 * 16; i += 256) {
        int c = i >> 4, seg = i & 15;
        *(uint4*)(Ws1 + c * WSTR + seg * 8) = __ldg((const uint4*)w1 + i);
        *(uint4*)(Ws2 + c * WSTR + seg * 8) = __ldg((const uint4*)w2 + i);
    }

    int warp = tid >> 5, lane = tid & 31;
    int gi = lane >> 2, ti = lane & 3;
    int mbase = warp * 16;

    int ntiles = (nrows + TR - 1) / TR;
    int stride = gridDim.x;

    uint4 reg[8];

    // prologue: tile blockIdx.x -> Xs0 (2048 uint4, 8 per thread)
    {
        long long r0 = (long long)blockIdx.x * TR;
#pragma unroll
        for (int p = 0; p < 8; p++) {
            int idx = tid + 256 * p;
            long long gr = r0 + (idx >> 4);
            reg[p] = (gr < nrows) ? __ldg((const uint4*)in + gr * 16 + (idx & 15))
                                  : make_uint4(0, 0, 0, 0);
        }
#pragma unroll
        for (int p = 0; p < 8; p++) {
            int idx = tid + 256 * p;
            *(uint4*)(Xs0 + (idx >> 4) * XSTR + (idx & 15) * 8) = reg[p];
        }
    }
    __syncthreads();

    __half* bufs[2] = {Xs0, Xs1};
    int buf = 0;

    for (int tt = blockIdx.x; tt < ntiles; tt += stride) {
        int nxt = tt + stride;
        if (nxt < ntiles) {
            long long r0 = (long long)nxt * TR;
#pragma unroll
            for (int p = 0; p < 8; p++) {
                int idx = tid + 256 * p;
                long long gr = r0 + (idx >> 4);
                reg[p] = (gr < nrows) ? __ldg((const uint4*)in + gr * 16 + (idx & 15))
                                      : make_uint4(0, 0, 0, 0);
            }
        }

        const __half* Xs = bufs[buf];

        // ---- MMA1: T[16 rows][128 cols] into acc1 ----
        float acc1[16][4];
#pragma unroll
        for (int j = 0; j < 16; j++)
#pragma unroll
            for (int q = 0; q < 4; q++) acc1[j][q] = 0.f;

#pragma unroll
        for (int kk = 0; kk < 8; kk++) {
            int k0 = kk * 16;
            unsigned a[4];
            int r = mbase + gi;
            a[0] = *(const unsigned*)(Xs + r * XSTR + k0 + 2 * ti);
            a[1] = *(const unsigned*)(Xs + (r + 8) * XSTR + k0 + 2 * ti);
            a[2] = *(const unsigned*)(Xs + r * XSTR + k0 + 2 * ti + 8);
            a[3] = *(const unsigned*)(Xs + (r + 8) * XSTR + k0 + 2 * ti + 8);
#pragma unroll
            for (int j = 0; j < 16; j++) {
                int c = j * 8 + gi;
                unsigned b[2];
                b[0] = *(const unsigned*)(Ws1 + c * WSTR + k0 + 2 * ti);
                b[1] = *(const unsigned*)(Ws1 + c * WSTR + k0 + 2 * ti + 8);
                mma_16x8x16(acc1[j], a, b);
            }
        }

        // ---- bias1 + relu + convert: C-frag -> A-frag (af) ----
        unsigned af[16][2];
#pragma unroll
        for (int j = 0; j < 16; j++) {
            int c0 = j * 8 + 2 * ti;
            float2 bb = __ldg((const float2*)(b1 + c0));
            float v0 = fmaxf(acc1[j][0] + bb.x, 0.f);
            float v1 = fmaxf(acc1[j][1] + bb.y, 0.f);
            float v2 = fmaxf(acc1[j][2] + bb.x, 0.f);
            float v3 = fmaxf(acc1[j][3] + bb.y, 0.f);
            __half2 lo = __floats2half2_rn(v0, v1);
            __half2 hi = __floats2half2_rn(v2, v3);
            af[j][0] = *(unsigned*)&lo;
            af[j][1] = *(unsigned*)&hi;
        }

        // ---- MMA2: out = T @ W2^T ----
        float acc2[16][4];
#pragma unroll
        for (int j = 0; j < 16; j++)
#pragma unroll
            for (int q = 0; q < 4; q++) acc2[j][q] = 0.f;

#pragma unroll
        for (int kk = 0; kk < 8; kk++) {
            int k0 = kk * 16;
            unsigned a[4] = {af[2 * kk][0], af[2 * kk][1],
                             af[2 * kk + 1][0], af[2 * kk + 1][1]};
#pragma unroll
            for (int j = 0; j < 16; j++) {
                int c = j * 8 + gi;
                unsigned b[2];
                b[0] = *(const unsigned*)(Ws2 + c * WSTR + k0 + 2 * ti);
                b[1] = *(const unsigned*)(Ws2 + c * WSTR + k0 + 2 * ti + 8);
                mma_16x8x16(acc2[j], a, b);
            }
        }

        // ---- epilogue: bias2, store ----
        long long row0 = (long long)tt * TR + mbase + gi;
#pragma unroll
        for (int j = 0; j < 16; j++) {
            int c0 = j * 8 + 2 * ti;
            float2 bb = __ldg((const float2*)(b2 + c0));
            float v0 = acc2[j][0] + bb.x;
            float v1 = acc2[j][1] + bb.y;
            float v2 = acc2[j][2] + bb.x;
            float v3 = acc2[j][3] + bb.y;
            if (outf) {
                if (row0 < nrows)
                    *(float2*)(outf + row0 * D + c0) = make_float2(v0, v1);
                if (row0 + 8 < nrows)
                    *(float2*)(outf + (row0 + 8) * D + c0) = make_float2(v2, v3);
            } else {
                if (row0 < nrows)
                    *(__half2*)(outh + row0 * D + c0) = __floats2half2_rn(v0, v1);
                if (row0 + 8 < nrows)
                    *(__half2*)(outh + (row0 + 8) * D + c0) = __floats2half2_rn(v2, v3);
            }
        }

        if (nxt < ntiles) {
#pragma unroll
            for (int p = 0; p < 8; p++) {
                int idx = tid + 256 * p;
                *(uint4*)(bufs[buf ^ 1] + (idx >> 4) * XSTR + (idx & 15) * 8) = reg[p];
            }
            __syncthreads();
            buf ^= 1;
        }
    }
}

// ---------------------------------------------------------------------------
extern "C" void kernel_launch(void* const* d_in, const int* in_sizes, int n_in,
                              void* d_out, int out_size) {
    const float* x   = (const float*)d_in[0];
    const int*   ei  = (const int*)d_in[1];
    const float* w0a = (const float*)d_in[2];
    const float* b0a = (const float*)d_in[3];
    const float* w0b = (const float*)d_in[4];
    const float* b0b = (const float*)d_in[5];
    const float* w1a = (const float*)d_in[6];
    const float* b1a = (const float*)d_in[7];
    const float* w1b = (const float*)d_in[8];
    const float* b1b = (const float*)d_in[9];

    int N = in_sizes[0] / D;
    int E = in_sizes[1] / 2;

    __half *p_xh, *p_hh, *p_oh, *p_wh;
    cudaGetSymbolAddress((void**)&p_xh, g_xh);
    cudaGetSymbolAddress((void**)&p_hh, g_hh);
    cudaGetSymbolAddress((void**)&p_oh, g_oh);
    cudaGetSymbolAddress((void**)&p_wh, g_wh);

    int nsm = 148;
    cudaDeviceGetAttribute(&nsm, cudaDevAttrMultiProcessorCount, 0);

    const int smem = (2 * 128 * WSTR + 2 * TR * XSTR) * (int)sizeof(__half);
    cudaFuncSetAttribute(layer_fused_kernel, cudaFuncAttributeMaxDynamicSharedMemorySize, smem);

    int nb = (N + 1023) / 1024;
    int gatherBlocks = (N + 7) / 8;
    int n4 = N * (D / 4);
    int e4 = (E + 3) / 4;

    convert_w_kernel<<<(4 * D * D + 255) / 256, 256>>>(w0a, w0b, w1a, w1b);
    convert_x_kernel<<<(n4 + 255) / 256, 256>>>(x, n4);

    // ---- CSR build ----
    zero_deg_kernel<<<(N + 255) / 256, 256>>>(N);
    hist_kernel<<<(e4 + 255) / 256, 256>>>(ei, E);
    scan1_kernel<<<nb, 1024>>>(N);
    scan2_kernel<<<1, 128>>>(nb);
    scan3_kernel<<<(N + 255) / 256, 256>>>(N, E);
    fill_kernel<<<(e4 + 255) / 256, 256>>>(ei, E);

    // ---- Layer 1 ----
    gather_h_kernel<<<gatherBlocks, 256>>>(p_xh, p_hh, N);
    layer_fused_kernel<<<nsm, 256, smem>>>(p_hh, p_wh + 0 * D * D, b0a,
                                           p_wh + 1 * D * D, b0b, p_oh, nullptr, N);

    // ---- Layer 2 ----
    gather_h_kernel<<<gatherBlocks, 256>>>(p_oh, p_hh, N);
    layer_fused_kernel<<<nsm, 256, smem>>>(p_hh, p_wh + 2 * D * D, b1a,
                                           p_wh + 3 * D * D, b1b, nullptr, (float*)d_out, N);
}